// round 1
// baseline (speedup 1.0000x reference)
#include <cuda_runtime.h>
#include <cstdint>

#define NN 40000
#define EE 640000
#define GG 64
#define DD 128
#define HH 128
#define OO 10

// ---------------- scratch (static device globals; no allocations) ----------------
__device__ float    g_h[NN * HH];        // x @ W_gcn
__device__ float    g_agg[NN * HH];      // edge-message accumulator
__device__ float    g_deg[NN];
__device__ float    g_dinv[NN];
__device__ float    g_addpool[GG * HH];
__device__ unsigned g_maxpool[GG * HH];  // order-preserving float encoding
__device__ int      g_counts[GG];

// order-preserving float <-> unsigned encoding for atomicMax
__device__ __forceinline__ unsigned fkey(float f) {
    int i = __float_as_int(f);
    return (unsigned)(i ^ ((i >> 31) | 0x80000000));
}
__device__ __forceinline__ float fdec(unsigned k) {
    int i = (k & 0x80000000u) ? (int)(k ^ 0x80000000u) : (int)(~k);
    return __int_as_float(i);
}

// ---------------- kernels ----------------
__global__ void k_init() {
    int i = blockIdx.x * blockDim.x + threadIdx.x;
    if (i < NN * HH) g_agg[i] = 0.f;
    if (i < NN)      g_deg[i] = 0.f;
    if (i < GG * HH) { g_addpool[i] = 0.f; g_maxpool[i] = 0u; }
    if (i < GG)      g_counts[i] = 0;
}

__global__ void k_deg(const int* __restrict__ ei) {
    int e = blockIdx.x * blockDim.x + threadIdx.x;
    if (e >= EE) return;
    atomicAdd(&g_deg[ei[EE + e]], 1.0f);
}

__global__ void k_dinv() {
    int n = blockIdx.x * blockDim.x + threadIdx.x;
    if (n < NN) g_dinv[n] = rsqrtf(g_deg[n] + 1.0f);
}

// h = x @ W. Block tile 64 rows x 128 cols, 256 threads, W fully in smem.
__global__ void k_gemm(const float* __restrict__ x, const float* __restrict__ W) {
    extern __shared__ float sm[];
    float* Ws = sm;                 // 128*128
    float* Xs = sm + DD * HH;       // 16 * 72 (transposed x tile)
    const int XLD = 72;
    int tid = threadIdx.x;
    int row0 = blockIdx.x * 64;

    // load full W (k-major, matches [D][H] row-major)
    for (int i = tid; i < (DD * HH) / 4; i += 256)
        ((float4*)Ws)[i] = ((const float4*)W)[i];

    int tx = tid & 31;              // col group: cols tx*4 .. tx*4+3
    int ty = tid >> 5;              // row group: rows ty*8 .. ty*8+7
    float acc[8][4];
#pragma unroll
    for (int r = 0; r < 8; r++)
#pragma unroll
        for (int c = 0; c < 4; c++) acc[r][c] = 0.f;

    int lr = tid >> 2, lk = tid & 3;  // x-tile loader coords
    for (int kt = 0; kt < DD; kt += 16) {
        __syncthreads();
        float4 xv = *(const float4*)(x + (size_t)(row0 + lr) * DD + kt + lk * 4);
        Xs[(lk * 4 + 0) * XLD + lr] = xv.x;
        Xs[(lk * 4 + 1) * XLD + lr] = xv.y;
        Xs[(lk * 4 + 2) * XLD + lr] = xv.z;
        Xs[(lk * 4 + 3) * XLD + lr] = xv.w;
        __syncthreads();
#pragma unroll
        for (int kk = 0; kk < 16; kk++) {
            float4 wv = *(const float4*)(Ws + (kt + kk) * HH + tx * 4);
            float4 xa = *(const float4*)(Xs + kk * XLD + ty * 8);
            float4 xb = *(const float4*)(Xs + kk * XLD + ty * 8 + 4);
            float xr[8] = {xa.x, xa.y, xa.z, xa.w, xb.x, xb.y, xb.z, xb.w};
#pragma unroll
            for (int r = 0; r < 8; r++) {
                acc[r][0] = fmaf(xr[r], wv.x, acc[r][0]);
                acc[r][1] = fmaf(xr[r], wv.y, acc[r][1]);
                acc[r][2] = fmaf(xr[r], wv.z, acc[r][2]);
                acc[r][3] = fmaf(xr[r], wv.w, acc[r][3]);
            }
        }
    }
#pragma unroll
    for (int r = 0; r < 8; r++) {
        float4 o = make_float4(acc[r][0], acc[r][1], acc[r][2], acc[r][3]);
        *(float4*)(g_h + (size_t)(row0 + ty * 8 + r) * HH + tx * 4) = o;
    }
}

// One warp per edge: gather h[src] row, scale, vector red-add into agg[dst].
__global__ void k_scatter(const int* __restrict__ ei) {
    int gid = blockIdx.x * blockDim.x + threadIdx.x;
    int e = gid >> 5;
    if (e >= EE) return;
    int lane = gid & 31;
    int src = __ldg(&ei[e]);
    int dst = __ldg(&ei[EE + e]);
    float c = g_dinv[src] * g_dinv[dst];
    float4 v = *(const float4*)(g_h + (size_t)src * HH + lane * 4);
    v.x *= c; v.y *= c; v.z *= c; v.w *= c;
    float* p = g_agg + (size_t)dst * HH + lane * 4;
    asm volatile("red.global.add.v4.f32 [%0], {%1, %2, %3, %4};"
                 :: "l"(p), "f"(v.x), "f"(v.y), "f"(v.z), "f"(v.w) : "memory");
}

// One warp per node: self-loop + bias + ReLU + LayerNorm, then pool atomics.
__global__ void k_node(const int* __restrict__ batch,
                       const float* __restrict__ bgcn,
                       const float* __restrict__ gamma,
                       const float* __restrict__ beta) {
    int gid = blockIdx.x * blockDim.x + threadIdx.x;
    int n = gid >> 5;
    if (n >= NN) return;
    int lane = gid & 31;
    int f = lane * 4;

    float4 a  = *(const float4*)(g_agg + (size_t)n * HH + f);
    float4 hv = *(const float4*)(g_h   + (size_t)n * HH + f);
    float di = g_dinv[n];
    float s2 = di * di;
    float4 bb = *(const float4*)(bgcn + f);
    float4 v;
    v.x = fmaxf(fmaf(hv.x, s2, a.x) + bb.x, 0.f);
    v.y = fmaxf(fmaf(hv.y, s2, a.y) + bb.y, 0.f);
    v.z = fmaxf(fmaf(hv.z, s2, a.z) + bb.z, 0.f);
    v.w = fmaxf(fmaf(hv.w, s2, a.w) + bb.w, 0.f);

    float s = v.x + v.y + v.z + v.w;
    float q = v.x * v.x + v.y * v.y + v.z * v.z + v.w * v.w;
#pragma unroll
    for (int o = 16; o; o >>= 1) {
        s += __shfl_xor_sync(0xffffffffu, s, o);
        q += __shfl_xor_sync(0xffffffffu, q, o);
    }
    float mean = s * (1.f / 128.f);
    float var  = q * (1.f / 128.f) - mean * mean;
    float rstd = rsqrtf(var + 1e-5f);

    float4 ga = *(const float4*)(gamma + f);
    float4 be = *(const float4*)(beta + f);
    float4 y;
    y.x = fmaf((v.x - mean) * rstd, ga.x, be.x);
    y.y = fmaf((v.y - mean) * rstd, ga.y, be.y);
    y.z = fmaf((v.z - mean) * rstd, ga.z, be.z);
    y.w = fmaf((v.w - mean) * rstd, ga.w, be.w);

    int g = __ldg(&batch[n]);
    float* p = g_addpool + g * HH + f;
    asm volatile("red.global.add.v4.f32 [%0], {%1, %2, %3, %4};"
                 :: "l"(p), "f"(y.x), "f"(y.y), "f"(y.z), "f"(y.w) : "memory");
    unsigned* mp = g_maxpool + g * HH + f;
    atomicMax(mp + 0, fkey(y.x));
    atomicMax(mp + 1, fkey(y.y));
    atomicMax(mp + 2, fkey(y.z));
    atomicMax(mp + 3, fkey(y.w));
    if (lane == 0) atomicAdd(&g_counts[g], 1);
}

// One block per graph: build [mean|add|max] then 384->128->64->10 MLP.
__global__ void k_final(const float* __restrict__ W1, const float* __restrict__ b1,
                        const float* __restrict__ W2, const float* __restrict__ b2,
                        const float* __restrict__ W3, const float* __restrict__ b3,
                        float* __restrict__ out) {
    __shared__ float gv[3 * HH];
    __shared__ float l1[HH];
    __shared__ float l2[HH / 2];
    int g = blockIdx.x;
    int t = threadIdx.x;  // 128

    int cnt = g_counts[g];
    float ad = g_addpool[g * HH + t];
    float mean = ad / fmaxf((float)cnt, 1.f);
    float mx = (cnt > 0) ? fdec(g_maxpool[g * HH + t]) : 0.f;
    gv[t] = mean;
    gv[HH + t] = ad;
    gv[2 * HH + t] = mx;
    __syncthreads();

    float acc = __ldg(&b1[t]);
    for (int k = 0; k < 3 * HH; k++)
        acc = fmaf(gv[k], __ldg(&W1[k * HH + t]), acc);
    l1[t] = fmaxf(acc, 0.f);
    __syncthreads();

    if (t < HH / 2) {
        float a2 = __ldg(&b2[t]);
        for (int k = 0; k < HH; k++)
            a2 = fmaf(l1[k], __ldg(&W2[k * (HH / 2) + t]), a2);
        l2[t] = fmaxf(a2, 0.f);
    }
    __syncthreads();

    if (t < OO) {
        float a3 = __ldg(&b3[t]);
        for (int k = 0; k < HH / 2; k++)
            a3 = fmaf(l2[k], __ldg(&W3[k * OO + t]), a3);
        out[g * OO + t] = a3;
    }
}

// ---------------- launch ----------------
extern "C" void kernel_launch(void* const* d_in, const int* in_sizes, int n_in,
                              void* d_out, int out_size) {
    const float* x     = (const float*)d_in[0];
    const int*   ei    = (const int*)d_in[1];
    const int*   batch = (const int*)d_in[2];
    // num_graphs may or may not be materialized as a size-1 input
    int idx = 3;
    if (n_in > 3 && in_sizes[3] == 1) idx = 4;
    const float* Wg    = (const float*)d_in[idx++];
    const float* bg    = (const float*)d_in[idx++];
    const float* gamma = (const float*)d_in[idx++];
    const float* beta  = (const float*)d_in[idx++];
    const float* W1    = (const float*)d_in[idx++];
    const float* b1    = (const float*)d_in[idx++];
    const float* W2    = (const float*)d_in[idx++];
    const float* b2    = (const float*)d_in[idx++];
    const float* W3    = (const float*)d_in[idx++];
    const float* b3    = (const float*)d_in[idx++];
    float* out = (float*)d_out;

    const int smem = (DD * HH + 16 * 72) * (int)sizeof(float);
    cudaFuncSetAttribute(k_gemm, cudaFuncAttributeMaxDynamicSharedMemorySize, smem);

    k_init<<<(NN * HH + 255) / 256, 256>>>();
    k_deg<<<(EE + 255) / 256, 256>>>(ei);
    k_dinv<<<(NN + 255) / 256, 256>>>();
    k_gemm<<<NN / 64, 256, smem>>>(x, Wg);
    k_scatter<<<EE / 8, 256>>>(ei);            // one warp per edge, 8 warps/block
    k_node<<<NN / 8, 256>>>(batch, bg, gamma, beta);
    k_final<<<GG, 128>>>(W1, b1, W2, b2, W3, b3, out);
}

// round 2
// speedup vs baseline: 1.0475x; 1.0475x over previous
#include <cuda_runtime.h>
#include <cstdint>
#include <cfloat>

#define NN 40000
#define EE 640000
#define GG 64
#define DD 128
#define HH 128
#define OO 10
#define NPW 8   // nodes per warp in k_agg

// ---------------- scratch (static device globals; no allocations) ----------------
__device__ float    g_h[NN * HH];      // x @ W_gcn (L2-resident, 20.5 MB)
__device__ int      g_degi[NN];
__device__ float    g_dinv[NN];
__device__ int      g_off[NN + 1];     // CSR row offsets (by dst)
__device__ int      g_cursor[NN];
__device__ int      g_esrc[EE];        // CSR: src node per edge slot
__device__ float    g_ecoef[EE];       // dinv[src] per edge slot
__device__ float    g_addpool[GG * HH];
__device__ unsigned g_maxpool[GG * HH];
__device__ int      g_counts[GG];

// order-preserving float <-> unsigned encoding for atomicMax
__device__ __forceinline__ unsigned fkey(float f) {
    int i = __float_as_int(f);
    return (unsigned)(i ^ ((i >> 31) | 0x80000000));
}
__device__ __forceinline__ float fdec(unsigned k) {
    int i = (k & 0x80000000u) ? (int)(k ^ 0x80000000u) : (int)(~k);
    return __int_as_float(i);
}

// ---------------- kernels ----------------
__global__ void k_init() {
    int i = blockIdx.x * blockDim.x + threadIdx.x;
    if (i < NN)      g_degi[i] = 0;
    if (i < GG * HH) { g_addpool[i] = 0.f; g_maxpool[i] = 0u; }
    if (i < GG)      g_counts[i] = 0;
}

__global__ void k_deg(const int* __restrict__ ei) {
    int e = blockIdx.x * blockDim.x + threadIdx.x;
    if (e >= EE) return;
    atomicAdd(&g_degi[ei[EE + e]], 1);
}

// Single-block scan over 40000 degree counts -> CSR offsets + cursors + dinv.
__global__ void k_scan() {
    __shared__ int s_sum[1024];
    const int CH = (NN + 1023) / 1024;     // 40
    int t = threadIdx.x;
    int base = t * CH;
    int s = 0;
#pragma unroll 8
    for (int i = 0; i < CH; i++) {
        int idx = base + i;
        if (idx < NN) s += g_degi[idx];
    }
    s_sum[t] = s;
    __syncthreads();
    for (int o = 1; o < 1024; o <<= 1) {
        int v = (t >= o) ? s_sum[t - o] : 0;
        __syncthreads();
        s_sum[t] += v;
        __syncthreads();
    }
    int run = (t > 0) ? s_sum[t - 1] : 0;
    for (int i = 0; i < CH; i++) {
        int idx = base + i;
        if (idx < NN) {
            int d = g_degi[idx];
            g_off[idx] = run;
            g_cursor[idx] = run;
            run += d;
            g_dinv[idx] = rsqrtf((float)d + 1.0f);
        }
    }
    if (t == (NN - 1) / CH) g_off[NN] = run;
}

__global__ void k_place(const int* __restrict__ ei) {
    int e = blockIdx.x * blockDim.x + threadIdx.x;
    if (e >= EE) return;
    int src = ei[e];
    int dst = ei[EE + e];
    int pos = atomicAdd(&g_cursor[dst], 1);
    g_esrc[pos] = src;
    g_ecoef[pos] = g_dinv[src];
}

// h = x @ W. Block tile 64 rows x 128 cols, 256 threads, W fully in smem.
__global__ void k_gemm(const float* __restrict__ x, const float* __restrict__ W) {
    extern __shared__ float sm[];
    float* Ws = sm;                 // 128*128
    float* Xs = sm + DD * HH;       // 16 * 72 (transposed x tile)
    const int XLD = 72;
    int tid = threadIdx.x;
    int row0 = blockIdx.x * 64;

    for (int i = tid; i < (DD * HH) / 4; i += 256)
        ((float4*)Ws)[i] = ((const float4*)W)[i];

    int tx = tid & 31;
    int ty = tid >> 5;
    float acc[8][4];
#pragma unroll
    for (int r = 0; r < 8; r++)
#pragma unroll
        for (int c = 0; c < 4; c++) acc[r][c] = 0.f;

    int lr = tid >> 2, lk = tid & 3;
    for (int kt = 0; kt < DD; kt += 16) {
        __syncthreads();
        float4 xv = *(const float4*)(x + (size_t)(row0 + lr) * DD + kt + lk * 4);
        Xs[(lk * 4 + 0) * XLD + lr] = xv.x;
        Xs[(lk * 4 + 1) * XLD + lr] = xv.y;
        Xs[(lk * 4 + 2) * XLD + lr] = xv.z;
        Xs[(lk * 4 + 3) * XLD + lr] = xv.w;
        __syncthreads();
#pragma unroll
        for (int kk = 0; kk < 16; kk++) {
            float4 wv = *(const float4*)(Ws + (kt + kk) * HH + tx * 4);
            float4 xa = *(const float4*)(Xs + kk * XLD + ty * 8);
            float4 xb = *(const float4*)(Xs + kk * XLD + ty * 8 + 4);
            float xr[8] = {xa.x, xa.y, xa.z, xa.w, xb.x, xb.y, xb.z, xb.w};
#pragma unroll
            for (int r = 0; r < 8; r++) {
                acc[r][0] = fmaf(xr[r], wv.x, acc[r][0]);
                acc[r][1] = fmaf(xr[r], wv.y, acc[r][1]);
                acc[r][2] = fmaf(xr[r], wv.z, acc[r][2]);
                acc[r][3] = fmaf(xr[r], wv.w, acc[r][3]);
            }
        }
    }
#pragma unroll
    for (int r = 0; r < 8; r++) {
        float4 o = make_float4(acc[r][0], acc[r][1], acc[r][2], acc[r][3]);
        *(float4*)(g_h + (size_t)(row0 + ty * 8 + r) * HH + tx * 4) = o;
    }
}

__device__ __forceinline__ void pool_flush(int g, int f, float4 padd, float4 pmax,
                                           int pcnt, int lane) {
    float* p = g_addpool + g * HH + f;
    asm volatile("red.global.add.v4.f32 [%0], {%1, %2, %3, %4};"
                 :: "l"(p), "f"(padd.x), "f"(padd.y), "f"(padd.z), "f"(padd.w)
                 : "memory");
    unsigned* mp = g_maxpool + g * HH + f;
    atomicMax(mp + 0, fkey(pmax.x));
    atomicMax(mp + 1, fkey(pmax.y));
    atomicMax(mp + 2, fkey(pmax.z));
    atomicMax(mp + 3, fkey(pmax.w));
    if (lane == 0) atomicAdd(&g_counts[g], pcnt);
}

// One warp per NPW consecutive nodes: CSR gather-reduce + self loop + bias +
// ReLU + LayerNorm + register-privatized pooling (batch is sorted by graph).
__global__ void __launch_bounds__(256) k_agg(const int* __restrict__ batch,
                                             const float* __restrict__ bgcn,
                                             const float* __restrict__ gamma,
                                             const float* __restrict__ beta) {
    int warp = blockIdx.x * 8 + (threadIdx.x >> 5);
    int n0 = warp * NPW;
    if (n0 >= NN) return;
    int lane = threadIdx.x & 31;
    int f = lane * 4;

    float4 bb = *(const float4*)(bgcn + f);
    float4 ga = *(const float4*)(gamma + f);
    float4 be = *(const float4*)(beta + f);

    float4 padd = make_float4(0.f, 0.f, 0.f, 0.f);
    float4 pmax = make_float4(-FLT_MAX, -FLT_MAX, -FLT_MAX, -FLT_MAX);
    int pcnt = 0;
    int curg = __ldg(&batch[n0]);

#pragma unroll
    for (int k = 0; k < NPW; k++) {
        int n = n0 + k;
        int g = __ldg(&batch[n]);
        if (g != curg) {
            pool_flush(curg, f, padd, pmax, pcnt, lane);
            padd = make_float4(0.f, 0.f, 0.f, 0.f);
            pmax = make_float4(-FLT_MAX, -FLT_MAX, -FLT_MAX, -FLT_MAX);
            pcnt = 0;
            curg = g;
        }
        int s = __ldg(&g_off[n]);
        int e = __ldg(&g_off[n + 1]);
        float4 acc = make_float4(0.f, 0.f, 0.f, 0.f);
        for (int j = s; j < e; j++) {
            int src = __ldg(&g_esrc[j]);
            float c  = __ldg(&g_ecoef[j]);
            float4 v = *(const float4*)(g_h + (size_t)src * HH + f);
            acc.x = fmaf(c, v.x, acc.x);
            acc.y = fmaf(c, v.y, acc.y);
            acc.z = fmaf(c, v.z, acc.z);
            acc.w = fmaf(c, v.w, acc.w);
        }
        float di = g_dinv[n];
        float4 hv = *(const float4*)(g_h + (size_t)n * HH + f);
        // total = di * (acc + hv*di) + b, then ReLU
        float4 v;
        v.x = fmaxf(fmaf(fmaf(hv.x, di, acc.x), di, bb.x), 0.f);
        v.y = fmaxf(fmaf(fmaf(hv.y, di, acc.y), di, bb.y), 0.f);
        v.z = fmaxf(fmaf(fmaf(hv.z, di, acc.z), di, bb.z), 0.f);
        v.w = fmaxf(fmaf(fmaf(hv.w, di, acc.w), di, bb.w), 0.f);

        float ssum = v.x + v.y + v.z + v.w;
        float qsum = v.x * v.x + v.y * v.y + v.z * v.z + v.w * v.w;
#pragma unroll
        for (int o = 16; o; o >>= 1) {
            ssum += __shfl_xor_sync(0xffffffffu, ssum, o);
            qsum += __shfl_xor_sync(0xffffffffu, qsum, o);
        }
        float mean = ssum * (1.f / 128.f);
        float var  = qsum * (1.f / 128.f) - mean * mean;
        float rstd = rsqrtf(var + 1e-5f);

        float4 y;
        y.x = fmaf((v.x - mean) * rstd, ga.x, be.x);
        y.y = fmaf((v.y - mean) * rstd, ga.y, be.y);
        y.z = fmaf((v.z - mean) * rstd, ga.z, be.z);
        y.w = fmaf((v.w - mean) * rstd, ga.w, be.w);

        padd.x += y.x; padd.y += y.y; padd.z += y.z; padd.w += y.w;
        pmax.x = fmaxf(pmax.x, y.x); pmax.y = fmaxf(pmax.y, y.y);
        pmax.z = fmaxf(pmax.z, y.z); pmax.w = fmaxf(pmax.w, y.w);
        pcnt++;
    }
    pool_flush(curg, f, padd, pmax, pcnt, lane);
}

// One block per graph: build [mean|add|max] then 384->128->64->10 MLP.
__global__ void k_final(const float* __restrict__ W1, const float* __restrict__ b1,
                        const float* __restrict__ W2, const float* __restrict__ b2,
                        const float* __restrict__ W3, const float* __restrict__ b3,
                        float* __restrict__ out) {
    __shared__ float gv[3 * HH];
    __shared__ float l1[HH];
    __shared__ float l2[HH / 2];
    int g = blockIdx.x;
    int t = threadIdx.x;  // 128

    int cnt = g_counts[g];
    float ad = g_addpool[g * HH + t];
    float mean = ad / fmaxf((float)cnt, 1.f);
    float mx = (cnt > 0) ? fdec(g_maxpool[g * HH + t]) : 0.f;
    gv[t] = mean;
    gv[HH + t] = ad;
    gv[2 * HH + t] = mx;
    __syncthreads();

    float acc = __ldg(&b1[t]);
    for (int k = 0; k < 3 * HH; k++)
        acc = fmaf(gv[k], __ldg(&W1[k * HH + t]), acc);
    l1[t] = fmaxf(acc, 0.f);
    __syncthreads();

    if (t < HH / 2) {
        float a2 = __ldg(&b2[t]);
        for (int k = 0; k < HH; k++)
            a2 = fmaf(l1[k], __ldg(&W2[k * (HH / 2) + t]), a2);
        l2[t] = fmaxf(a2, 0.f);
    }
    __syncthreads();

    if (t < OO) {
        float a3 = __ldg(&b3[t]);
        for (int k = 0; k < HH / 2; k++)
            a3 = fmaf(l2[k], __ldg(&W3[k * OO + t]), a3);
        out[g * OO + t] = a3;
    }
}

// ---------------- launch ----------------
extern "C" void kernel_launch(void* const* d_in, const int* in_sizes, int n_in,
                              void* d_out, int out_size) {
    const float* x     = (const float*)d_in[0];
    const int*   ei    = (const int*)d_in[1];
    const int*   batch = (const int*)d_in[2];
    int idx = 3;
    if (n_in > 3 && in_sizes[3] == 1) idx = 4;
    const float* Wg    = (const float*)d_in[idx++];
    const float* bg    = (const float*)d_in[idx++];
    const float* gamma = (const float*)d_in[idx++];
    const float* beta  = (const float*)d_in[idx++];
    const float* W1    = (const float*)d_in[idx++];
    const float* b1    = (const float*)d_in[idx++];
    const float* W2    = (const float*)d_in[idx++];
    const float* b2    = (const float*)d_in[idx++];
    const float* W3    = (const float*)d_in[idx++];
    const float* b3    = (const float*)d_in[idx++];
    float* out = (float*)d_out;

    const int smem = (DD * HH + 16 * 72) * (int)sizeof(float);
    cudaFuncSetAttribute(k_gemm, cudaFuncAttributeMaxDynamicSharedMemorySize, smem);

    k_init<<<(NN + 255) / 256, 256>>>();
    k_deg<<<(EE + 255) / 256, 256>>>(ei);
    k_scan<<<1, 1024>>>();
    k_place<<<(EE + 255) / 256, 256>>>(ei);
    k_gemm<<<NN / 64, 256, smem>>>(x, Wg);
    k_agg<<<NN / (NPW * 8), 256>>>(batch, bg, gamma, beta);
    k_final<<<GG, 128>>>(W1, b1, W2, b2, W3, b3, out);
}